// round 3
// baseline (speedup 1.0000x reference)
#include <cuda_runtime.h>
#include <mma.h>
#include <cstdint>
#include <math.h>

using namespace nvcuda;

// Problem constants
#define BB 2
#define NN 2048
#define CC 1024
#define HH 16
#define DD 64
#define INNER 1024
#define QK_SCALE 0.125f

// Scratch
__device__ float g_qkv[(size_t)BB * NN * 3 * INNER];   // [4096, 3072]
__device__ float g_attn[(size_t)BB * NN * INNER];      // [4096, 1024]

// ---------------------------------------------------------------------------
// Helpers
// ---------------------------------------------------------------------------
__device__ __forceinline__ uint32_t smem_u32(const void* p) {
    uint32_t a;
    asm("{ .reg .u64 t; cvta.to.shared.u64 t, %1; cvt.u32.u64 %0, t; }"
        : "=r"(a) : "l"(p));
    return a;
}
__device__ __forceinline__ float f2tf32(float x) {
    uint32_t u;
    asm("cvt.rna.tf32.f32 %0, %1;" : "=r"(u) : "f"(x));
    return __uint_as_float(u);
}
__device__ __forceinline__ void cp16(uint32_t dst, const void* src) {
    asm volatile("cp.async.cg.shared.global [%0], [%1], 16;"
                 :: "r"(dst), "l"(src));
}
#define CP_COMMIT() asm volatile("cp.async.commit_group;" ::: "memory")
#define CP_WAIT1()  asm volatile("cp.async.wait_group 1;" ::: "memory")

typedef wmma::fragment<wmma::matrix_a, 16, 16, 8, wmma::precision::tf32, wmma::row_major> FragA;
typedef wmma::fragment<wmma::matrix_b, 16, 16, 8, wmma::precision::tf32, wmma::col_major> FragBc;
typedef wmma::fragment<wmma::matrix_b, 16, 16, 8, wmma::precision::tf32, wmma::row_major> FragBr;
typedef wmma::fragment<wmma::accumulator, 16, 16, 8, float> FragC;

template <class F>
__device__ __forceinline__ void split3(const F& raw, F& hi, F& lo) {
#pragma unroll
    for (int i = 0; i < raw.num_elements; i++) {
        float v = raw.x[i];
        float h = f2tf32(v);
        hi.x[i] = h;
        lo.x[i] = f2tf32(v - h);
    }
}
template <class FB>
__device__ __forceinline__ void mma3(FragC& c, const FragA& ah, const FragA& al,
                                     const FB& bh, const FB& bl) {
    wmma::mma_sync(c, ah, bh, c);
    wmma::mma_sync(c, ah, bl, c);
    wmma::mma_sync(c, al, bh, c);
}

// ---------------------------------------------------------------------------
// tf32 wmma GEMM: C[M,N] = A[M,K] @ B[K,N] (+bias). 128x128 tile, 256 thr,
// K-step 32, cp.async 2-stage pipeline, 3xTF32 split in registers.
// ---------------------------------------------------------------------------
#define AST 36                          // A smem pitch (floats)
#define BST 132                         // B smem pitch (floats)
#define A_BYTES (128 * AST * 4)         // 18432
#define B_BYTES (32 * BST * 4)          // 16896
#define STAGE_BYTES (A_BYTES + B_BYTES) // 35328
#define GEMM_SMEM (2 * STAGE_BYTES)     // 70656 (>= 128*128*4 for epilogue reuse)

__device__ __forceinline__ void gemm_issue(
    uint32_t sb, const float* Ap, const float* Bm,
    int m0, int n0, int K, int N, int kt, int tid)
{
    uint32_t as = sb + (uint32_t)(kt & 1) * STAGE_BYTES;
    uint32_t bs = as + A_BYTES;
    const float* Ag = Ap + (size_t)m0 * K + kt * 32;
    const float* Bg = Bm + (size_t)(kt * 32) * N + n0;
#pragma unroll
    for (int i = 0; i < 4; i++) {
        int idx = tid + i * 256;        // 1024 float4 for A (128 rows x 8)
        int r = idx >> 3, f = idx & 7;
        cp16(as + (uint32_t)(r * AST + f * 4) * 4, Ag + (size_t)r * K + f * 4);
    }
#pragma unroll
    for (int i = 0; i < 4; i++) {
        int idx = tid + i * 256;        // 1024 float4 for B (32 rows x 32)
        int r = idx >> 5, f = idx & 31;
        cp16(bs + (uint32_t)(r * BST + f * 4) * 4, Bg + (size_t)r * N + f * 4);
    }
}

__global__ __launch_bounds__(256) void gemm_tc(
    const float* __restrict__ A, const float* __restrict__ Bm,
    float* __restrict__ Cout, const float* __restrict__ bias,
    int M, int N, int K, int aFromAttn, int cToQkv)
{
    extern __shared__ char sm[];
    const float* __restrict__ Ap = aFromAttn ? g_attn : A;
    float* __restrict__ Cp = cToQkv ? g_qkv : Cout;

    const uint32_t sb = smem_u32(sm);
    const int tid = threadIdx.x;
    const int wid = tid >> 5;
    const int wm = wid & 3;        // 4 warps along M (4*32 = 128)
    const int wn = wid >> 2;       // 2 warps along N (2*64 = 128)
    const int m0 = blockIdx.y * 128;
    const int n0 = blockIdx.x * 128;

    FragC acc[2][4];
#pragma unroll
    for (int i = 0; i < 2; i++)
#pragma unroll
        for (int j = 0; j < 4; j++) wmma::fill_fragment(acc[i][j], 0.0f);

    const int nkt = K / 32;
    gemm_issue(sb, Ap, Bm, m0, n0, K, N, 0, tid); CP_COMMIT();
    gemm_issue(sb, Ap, Bm, m0, n0, K, N, 1, tid); CP_COMMIT();

    for (int kt = 0; kt < nkt; kt++) {
        CP_WAIT1();
        __syncthreads();
        const float* as = (const float*)(sm + (size_t)(kt & 1) * STAGE_BYTES);
        const float* bs = as + 128 * AST;

#pragma unroll
        for (int s = 0; s < 4; s++) {
            FragA ahi[2], alo[2];
#pragma unroll
            for (int i = 0; i < 2; i++) {
                FragA ar;
                wmma::load_matrix_sync(ar, as + (wm * 32 + i * 16) * AST + s * 8, AST);
                split3(ar, ahi[i], alo[i]);
            }
#pragma unroll
            for (int j = 0; j < 4; j++) {
                FragBr br, bh, bl;
                wmma::load_matrix_sync(br, bs + (s * 8) * BST + wn * 64 + j * 16, BST);
                split3(br, bh, bl);
#pragma unroll
                for (int i = 0; i < 2; i++) mma3(acc[i][j], ahi[i], alo[i], bh, bl);
            }
        }
        __syncthreads();
        if (kt + 2 < nkt) gemm_issue(sb, Ap, Bm, m0, n0, K, N, kt + 2, tid);
        CP_COMMIT();
    }

    // Epilogue: stage through smem (reuse pipeline buffers), add bias, write.
    float* Cs = (float*)sm;
#pragma unroll
    for (int i = 0; i < 2; i++)
#pragma unroll
        for (int j = 0; j < 4; j++)
            wmma::store_matrix_sync(Cs + (wm * 32 + i * 16) * 128 + wn * 64 + j * 16,
                                    acc[i][j], 128, wmma::mem_row_major);
    __syncthreads();
#pragma unroll
    for (int i = 0; i < 16; i++) {
        int idx = tid + i * 256;      // 4096 float4 = 128x128
        int r = idx >> 5, f = idx & 31;
        float4 v = *(float4*)(Cs + r * 128 + f * 4);
        if (bias) {
            const float* bp = bias + n0 + f * 4;
            v.x += bp[0]; v.y += bp[1]; v.z += bp[2]; v.w += bp[3];
        }
        *(float4*)(Cp + (size_t)(m0 + r) * N + n0 + f * 4) = v;
    }
}

// ---------------------------------------------------------------------------
// Flash attention with wmma tf32 (3x split) for QK^T and PV.
// Block = (b, h, 64-query tile); 256 threads = 8 warps (4 along q, 2 along k/d).
// ---------------------------------------------------------------------------
#define FP 68                                    // smem pitch (floats)
#define FLASH_SMEM (5 * 64 * FP * 4 + 3 * 256)   // Q,K,V,S,O + m,l,alpha = 87808

__global__ __launch_bounds__(256) void flashtc()
{
    extern __shared__ char sm[];
    float* Qs = (float*)sm;              // [64][68]
    float* Ks = Qs + 64 * FP;
    float* Vs = Ks + 64 * FP;
    float* Ss = Vs + 64 * FP;
    float* Os = Ss + 64 * FP;
    float* mrow = Os + 64 * FP;          // [64]
    float* lrow = mrow + 64;
    float* arow = lrow + 64;

    const int tid = threadIdx.x;
    const int wid = tid >> 5;
    const int wm = wid & 3;              // q-dir: 4 x 16 = 64
    const int wn = wid >> 2;             // k/d-dir: 2 x 32 = 64
    const int b = blockIdx.y >> 4;
    const int h = blockIdx.y & 15;
    const int q0 = blockIdx.x * 64;

    // Load Q tile (scaled), zero O tile
    const float* qg = g_qkv + ((size_t)(b * NN + q0)) * 3072 + h * DD;
#pragma unroll
    for (int i = 0; i < 4; i++) {
        int idx = tid + i * 256;          // 1024 float4
        int r = idx >> 4, f = idx & 15;
        float4 v = *(const float4*)(qg + (size_t)r * 3072 + f * 4);
        v.x *= QK_SCALE; v.y *= QK_SCALE; v.z *= QK_SCALE; v.w *= QK_SCALE;
        *(float4*)(Qs + r * FP + f * 4) = v;
        *(float4*)(Os + r * FP + f * 4) = make_float4(0.f, 0.f, 0.f, 0.f);
    }
    if (tid < 64) { mrow[tid] = -INFINITY; lrow[tid] = 0.0f; }

    for (int kt = 0; kt < 32; kt++) {
        __syncthreads();   // prev iter done with Ks/Vs/Ss
        // Load K and V tiles (64 x 64 each)
        const float* kg = g_qkv + ((size_t)(b * NN + kt * 64)) * 3072 + INNER + h * DD;
#pragma unroll
        for (int i = 0; i < 8; i++) {
            int idx = tid + i * 256;      // 2048 float4
            int sel = idx >> 10;          // 0 = K, 1 = V
            int e = idx & 1023;
            int r = e >> 4, f = e & 15;
            const float4 v = *(const float4*)(kg + (size_t)r * 3072 + sel * INNER + f * 4);
            *(float4*)((sel ? Vs : Ks) + r * FP + f * 4) = v;
        }
        __syncthreads();

        // ---- S = Q K^T ----
        {
            FragC c[2];
            wmma::fill_fragment(c[0], 0.0f);
            wmma::fill_fragment(c[1], 0.0f);
#pragma unroll
            for (int s = 0; s < 8; s++) {
                FragA ar, ah, al;
                wmma::load_matrix_sync(ar, Qs + wm * 16 * FP + s * 8, FP);
                split3(ar, ah, al);
#pragma unroll
                for (int j = 0; j < 2; j++) {
                    FragBc br, bh, bl;   // B(k=d, n=krow) = Ks[n][d]  (col-major view)
                    wmma::load_matrix_sync(br, Ks + (wn * 32 + j * 16) * FP + s * 8, FP);
                    split3(br, bh, bl);
                    mma3(c[j], ah, al, bh, bl);
                }
            }
#pragma unroll
            for (int j = 0; j < 2; j++)
                wmma::store_matrix_sync(Ss + wm * 16 * FP + wn * 32 + j * 16,
                                        c[j], FP, wmma::mem_row_major);
        }
        __syncthreads();

        // ---- online softmax (4 lanes per row, 16 cols each) ----
        {
            int r = tid >> 2, ln = tid & 3;
            float* sp = Ss + r * FP + ln * 16;
            float4 s0 = *(float4*)(sp + 0),  s1 = *(float4*)(sp + 4);
            float4 s2 = *(float4*)(sp + 8),  s3 = *(float4*)(sp + 12);
            float mx = fmaxf(fmaxf(fmaxf(s0.x, s0.y), fmaxf(s0.z, s0.w)),
                             fmaxf(fmaxf(s1.x, s1.y), fmaxf(s1.z, s1.w)));
            mx = fmaxf(mx, fmaxf(fmaxf(fmaxf(s2.x, s2.y), fmaxf(s2.z, s2.w)),
                                 fmaxf(fmaxf(s3.x, s3.y), fmaxf(s3.z, s3.w))));
            mx = fmaxf(mx, __shfl_xor_sync(0xffffffffu, mx, 1));
            mx = fmaxf(mx, __shfl_xor_sync(0xffffffffu, mx, 2));
            float mo = mrow[r];
            float mn = fmaxf(mo, mx);
            float sum = 0.0f;
            s0.x = __expf(s0.x - mn); sum += s0.x; s0.y = __expf(s0.y - mn); sum += s0.y;
            s0.z = __expf(s0.z - mn); sum += s0.z; s0.w = __expf(s0.w - mn); sum += s0.w;
            s1.x = __expf(s1.x - mn); sum += s1.x; s1.y = __expf(s1.y - mn); sum += s1.y;
            s1.z = __expf(s1.z - mn); sum += s1.z; s1.w = __expf(s1.w - mn); sum += s1.w;
            s2.x = __expf(s2.x - mn); sum += s2.x; s2.y = __expf(s2.y - mn); sum += s2.y;
            s2.z = __expf(s2.z - mn); sum += s2.z; s2.w = __expf(s2.w - mn); sum += s2.w;
            s3.x = __expf(s3.x - mn); sum += s3.x; s3.y = __expf(s3.y - mn); sum += s3.y;
            s3.z = __expf(s3.z - mn); sum += s3.z; s3.w = __expf(s3.w - mn); sum += s3.w;
            sum += __shfl_xor_sync(0xffffffffu, sum, 1);
            sum += __shfl_xor_sync(0xffffffffu, sum, 2);
            *(float4*)(sp + 0) = s0;  *(float4*)(sp + 4) = s1;
            *(float4*)(sp + 8) = s2;  *(float4*)(sp + 12) = s3;
            if (ln == 0) {
                float alpha = __expf(mo - mn);
                lrow[r] = lrow[r] * alpha + sum;
                mrow[r] = mn;
                arow[r] = alpha;
            }
        }
        __syncthreads();

        // ---- rescale O by alpha ----
        {
            int r = tid >> 2, ln = tid & 3;
            float a_ = arow[r];
            float* op = Os + r * FP + ln * 16;
#pragma unroll
            for (int f = 0; f < 4; f++) {
                float4 v = *(float4*)(op + f * 4);
                v.x *= a_; v.y *= a_; v.z *= a_; v.w *= a_;
                *(float4*)(op + f * 4) = v;
            }
        }
        __syncthreads();

        // ---- O += P V ----
        {
            FragC c[2];
#pragma unroll
            for (int j = 0; j < 2; j++)
                wmma::load_matrix_sync(c[j], Os + wm * 16 * FP + wn * 32 + j * 16,
                                       FP, wmma::mem_row_major);
#pragma unroll
            for (int s = 0; s < 8; s++) {
                FragA pr, ph, pl;
                wmma::load_matrix_sync(pr, Ss + wm * 16 * FP + s * 8, FP);
                split3(pr, ph, pl);
#pragma unroll
                for (int j = 0; j < 2; j++) {
                    FragBr vr, vh, vl;   // B(k, n=d) = Vs[k][d]  (row-major)
                    wmma::load_matrix_sync(vr, Vs + (s * 8) * FP + wn * 32 + j * 16, FP);
                    split3(vr, vh, vl);
                    mma3(c[j], ph, pl, vh, vl);
                }
            }
#pragma unroll
            for (int j = 0; j < 2; j++)
                wmma::store_matrix_sync(Os + wm * 16 * FP + wn * 32 + j * 16,
                                        c[j], FP, wmma::mem_row_major);
        }
    }
    __syncthreads();

    // Epilogue: normalize, write to g_attn [B, N, H*D]
    {
        int r = tid >> 2, ln = tid & 3;
        float inv = 1.0f / lrow[r];
        float* op = Os + r * FP + ln * 16;
        float* og = g_attn + ((size_t)(b * NN + q0 + r)) * INNER + h * DD + ln * 16;
#pragma unroll
        for (int f = 0; f < 4; f++) {
            float4 v = *(float4*)(op + f * 4);
            v.x *= inv; v.y *= inv; v.z *= inv; v.w *= inv;
            *(float4*)(og + f * 4) = v;
        }
    }
}

// ---------------------------------------------------------------------------
extern "C" void kernel_launch(void* const* d_in, const int* in_sizes, int n_in,
                              void* d_out, int out_size)
{
    const float* x      = (const float*)d_in[0];  // [2, 2048, 1024]
    const float* w_qkv  = (const float*)d_in[1];  // [1024, 3072]
    const float* w_proj = (const float*)d_in[2];  // [1024, 1024]
    const float* b_proj = (const float*)d_in[3];  // [1024]
    float* out = (float*)d_out;

    cudaFuncSetAttribute(gemm_tc, cudaFuncAttributeMaxDynamicSharedMemorySize,
                         GEMM_SMEM);
    cudaFuncSetAttribute(flashtc, cudaFuncAttributeMaxDynamicSharedMemorySize,
                         FLASH_SMEM);

    // 1) qkv = x @ w_qkv -> g_qkv     (M=4096, N=3072, K=1024)
    gemm_tc<<<dim3(24, 32), 256, GEMM_SMEM>>>(x, w_qkv, nullptr, nullptr,
                                              4096, 3072, 1024, 0, 1);
    // 2) flash attention  g_qkv -> g_attn
    flashtc<<<dim3(32, 32), 256, FLASH_SMEM>>>();
    // 3) out = g_attn @ w_proj + b_proj (M=4096, N=1024, K=1024)
    gemm_tc<<<dim3(8, 32), 256, GEMM_SMEM>>>(nullptr, w_proj, out, b_proj,
                                             4096, 1024, 1024, 1, 0);
}

// round 4
// speedup vs baseline: 2.9818x; 2.9818x over previous
#include <cuda_runtime.h>
#include <cuda_fp16.h>
#include <mma.h>
#include <cstdint>
#include <math.h>

using namespace nvcuda;

// Problem constants
#define BB 2
#define NN 2048
#define CC 1024
#define HH 16
#define DD 64
#define INNER 1024
#define QK_SCALE 0.125f

// ---------------------------------------------------------------------------
// Global scratch: fp16 hi/lo split arrays (split once, consumed by MMAs)
// ---------------------------------------------------------------------------
__device__ __half g_xh[4194304],  g_xl[4194304];    // x        [4096,1024]
__device__ __half g_wqh[3145728], g_wql[3145728];   // w_qkv    [1024,3072]
__device__ __half g_wph[1048576], g_wpl[1048576];   // w_proj   [1024,1024]
__device__ __half g_qkvh[12582912], g_qkvl[12582912]; // qkv    [4096,3072]
__device__ __half g_ath[4194304], g_atl[4194304];   // attn out [4096,1024]

// ---------------------------------------------------------------------------
// Helpers
// ---------------------------------------------------------------------------
__device__ __forceinline__ uint32_t smem_u32(const void* p) {
    uint32_t a;
    asm("{ .reg .u64 t; cvta.to.shared.u64 t, %1; cvt.u32.u64 %0, t; }"
        : "=r"(a) : "l"(p));
    return a;
}
__device__ __forceinline__ void cp16(uint32_t dst, const void* src) {
    asm volatile("cp.async.cg.shared.global [%0], [%1], 16;"
                 :: "r"(dst), "l"(src));
}
#define CP_COMMIT() asm volatile("cp.async.commit_group;" ::: "memory")
#define CP_WAIT1()  asm volatile("cp.async.wait_group 1;" ::: "memory")
#define CP_WAIT0()  asm volatile("cp.async.wait_group 0;" ::: "memory")

typedef wmma::fragment<wmma::matrix_a, 16, 16, 16, __half, wmma::row_major> HA;
typedef wmma::fragment<wmma::matrix_b, 16, 16, 16, __half, wmma::row_major> HBr;
typedef wmma::fragment<wmma::matrix_b, 16, 16, 16, __half, wmma::col_major> HBc;
typedef wmma::fragment<wmma::accumulator, 16, 16, 16, float> HC;

__device__ __forceinline__ void split1(float v, __half& h, __half& l) {
    h = __float2half_rn(v);
    l = __float2half_rn(v - __half2float(h));
}

// ---------------------------------------------------------------------------
// Pre-split kernel: fp32 -> (hi, lo) fp16 arrays. Vectorized float4.
// ---------------------------------------------------------------------------
__global__ __launch_bounds__(256) void splitk(
    const float* __restrict__ s, __half* __restrict__ hi,
    __half* __restrict__ lo, int n4)
{
    int i = blockIdx.x * 256 + threadIdx.x;
    if (i >= n4) return;
    float4 v = ((const float4*)s)[i];
    __half h0, h1, h2, h3, l0, l1, l2, l3;
    split1(v.x, h0, l0); split1(v.y, h1, l1);
    split1(v.z, h2, l2); split1(v.w, h3, l3);
    ((__half2*)hi)[2 * i]     = __halves2half2(h0, h1);
    ((__half2*)hi)[2 * i + 1] = __halves2half2(h2, h3);
    ((__half2*)lo)[2 * i]     = __halves2half2(l0, l1);
    ((__half2*)lo)[2 * i + 1] = __halves2half2(l2, l3);
}

// ---------------------------------------------------------------------------
// fp16 split GEMM: C[M,N] = A[M,K] @ B[K,N]. 128x128 tile, 256 thr, K-step 32,
// cp.async 2-stage. 3-term: Ah*Bh + Ah*Bl + Al*Bh (fp32 accumulate).
// mode 0: write half hi/lo (Ch/Cl), scaling cols<1024 by QK_SCALE (q of qkv).
// mode 1: write fp32 + bias.
// ---------------------------------------------------------------------------
#define GP_A 40                         // A smem pitch (halves)
#define GP_B 136                        // B smem pitch (halves)
#define A_HALF (128 * GP_A)             // 5120
#define B_HALF (32 * GP_B)              // 4352
#define G_ABYTES (A_HALF * 2)           // 10240
#define G_BBYTES (B_HALF * 2)           // 8704
#define G_STAGE (2 * G_ABYTES + 2 * G_BBYTES)  // 37888
#define G_SMEM (2 * G_STAGE)            // 75776 (>= 65536 epilogue staging)

__device__ __forceinline__ void g_issue(
    uint32_t sb, const __half* Ah, const __half* Al,
    const __half* Bh, const __half* Bl,
    int m0, int n0, int K, int N, int kt, int tid)
{
    uint32_t st = sb + (uint32_t)(kt & 1) * G_STAGE;
#pragma unroll
    for (int i = 0; i < 4; i++) {        // A: 128 rows x 4 chunks x {hi,lo}
        int idx = tid + i * 256;
        int arr = idx >> 9, e = idx & 511;
        int r = e >> 2, f = e & 3;
        const __half* src = (arr ? Al : Ah) + (size_t)(m0 + r) * K + kt * 32 + f * 8;
        cp16(st + (uint32_t)arr * G_ABYTES + (uint32_t)(r * GP_A + f * 8) * 2, src);
    }
#pragma unroll
    for (int i = 0; i < 4; i++) {        // B: 32 rows x 16 chunks x {hi,lo}
        int idx = tid + i * 256;
        int arr = idx >> 9, e = idx & 511;
        int r = e >> 4, f = e & 15;
        const __half* src = (arr ? Bl : Bh) + (size_t)(kt * 32 + r) * N + n0 + f * 8;
        cp16(st + 2 * G_ABYTES + (uint32_t)arr * G_BBYTES
                + (uint32_t)(r * GP_B + f * 8) * 2, src);
    }
}

__global__ __launch_bounds__(256) void gemm_h(
    const __half* __restrict__ Ah, const __half* __restrict__ Al,
    const __half* __restrict__ Bh, const __half* __restrict__ Bl,
    float* __restrict__ Cout, const float* __restrict__ bias,
    __half* __restrict__ Ch, __half* __restrict__ Cl,
    int M, int N, int K, int mode)
{
    extern __shared__ char sm[];
    const uint32_t sb = smem_u32(sm);
    const int tid = threadIdx.x;
    const int wid = tid >> 5;
    const int wm = wid & 3;      // 4 warps along M: 4*32 = 128
    const int wn = wid >> 2;     // 2 warps along N: 2*64 = 128
    const int m0 = blockIdx.y * 128;
    const int n0 = blockIdx.x * 128;

    HC acc[2][4];
#pragma unroll
    for (int i = 0; i < 2; i++)
#pragma unroll
        for (int j = 0; j < 4; j++) wmma::fill_fragment(acc[i][j], 0.0f);

    const int nkt = K / 32;
    g_issue(sb, Ah, Al, Bh, Bl, m0, n0, K, N, 0, tid); CP_COMMIT();
    g_issue(sb, Ah, Al, Bh, Bl, m0, n0, K, N, 1, tid); CP_COMMIT();

    for (int kt = 0; kt < nkt; kt++) {
        CP_WAIT1();
        __syncthreads();
        const __half* st  = (const __half*)(sm + (size_t)(kt & 1) * G_STAGE);
        const __half* Ash = st;
        const __half* Asl = st + A_HALF;
        const __half* Bsh = st + 2 * A_HALF;
        const __half* Bsl = st + 2 * A_HALF + B_HALF;

#pragma unroll
        for (int s = 0; s < 2; s++) {
            HA ah[2], al[2];
#pragma unroll
            for (int i = 0; i < 2; i++) {
                wmma::load_matrix_sync(ah[i], Ash + (wm * 32 + i * 16) * GP_A + s * 16, GP_A);
                wmma::load_matrix_sync(al[i], Asl + (wm * 32 + i * 16) * GP_A + s * 16, GP_A);
            }
#pragma unroll
            for (int j = 0; j < 4; j++) {
                HBr bh, bl;
                wmma::load_matrix_sync(bh, Bsh + (s * 16) * GP_B + wn * 64 + j * 16, GP_B);
                wmma::load_matrix_sync(bl, Bsl + (s * 16) * GP_B + wn * 64 + j * 16, GP_B);
#pragma unroll
                for (int i = 0; i < 2; i++) {
                    wmma::mma_sync(acc[i][j], ah[i], bh, acc[i][j]);
                    wmma::mma_sync(acc[i][j], ah[i], bl, acc[i][j]);
                    wmma::mma_sync(acc[i][j], al[i], bh, acc[i][j]);
                }
            }
        }
        __syncthreads();
        if (kt + 2 < nkt)
            g_issue(sb, Ah, Al, Bh, Bl, m0, n0, K, N, kt + 2, tid);
        CP_COMMIT();
    }
    CP_WAIT0();
    __syncthreads();

    // Epilogue: stage through smem (reuse pipeline buffers)
    float* Cs = (float*)sm;
#pragma unroll
    for (int i = 0; i < 2; i++)
#pragma unroll
        for (int j = 0; j < 4; j++)
            wmma::store_matrix_sync(Cs + (wm * 32 + i * 16) * 128 + wn * 64 + j * 16,
                                    acc[i][j], 128, wmma::mem_row_major);
    __syncthreads();
#pragma unroll
    for (int i = 0; i < 16; i++) {
        int idx = tid + i * 256;
        int r = idx >> 5, f = idx & 31;
        float4 v = *(float4*)(Cs + r * 128 + f * 4);
        int gc = n0 + f * 4;
        if (mode == 1) {
            const float* bp = bias + gc;
            v.x += bp[0]; v.y += bp[1]; v.z += bp[2]; v.w += bp[3];
            *(float4*)(Cout + (size_t)(m0 + r) * N + gc) = v;
        } else {
            float sc = (gc < 1024) ? QK_SCALE : 1.0f;   // pre-scale q columns
            v.x *= sc; v.y *= sc; v.z *= sc; v.w *= sc;
            __half h0, h1, h2, h3, l0, l1, l2, l3;
            split1(v.x, h0, l0); split1(v.y, h1, l1);
            split1(v.z, h2, l2); split1(v.w, h3, l3);
            __half2* ph = (__half2*)(Ch + (size_t)(m0 + r) * N + gc);
            __half2* pl = (__half2*)(Cl + (size_t)(m0 + r) * N + gc);
            ph[0] = __halves2half2(h0, h1); ph[1] = __halves2half2(h2, h3);
            pl[0] = __halves2half2(l0, l1); pl[1] = __halves2half2(l2, l3);
        }
    }
}

// ---------------------------------------------------------------------------
// Flash attention, fp16 wmma. Block = (b,h,64-q-tile), 256 threads = 8 warps
// (wm = 4 along q-rows, wn = 2 along kv/d cols).  QK 3-term, PV 2-term.
// ---------------------------------------------------------------------------
#define FQP 72     // half-tile pitch (halves)
#define FSP 68     // fp32-tile pitch (floats)
#define FT_HALF (64 * FQP)               // 4608 halves = 9216 B per tile
#define F_SS 64512                       // byte offsets
#define F_OS 81920
#define F_MR 99328
#define F_SMEM 99840

__global__ __launch_bounds__(256) void flash_h()
{
    extern __shared__ char sm[];
    __half* Qh = (__half*)sm;
    __half* Ql = Qh + FT_HALF;
    __half* Kh = Qh + 2 * FT_HALF;
    __half* Kl = Qh + 3 * FT_HALF;
    __half* Vh = Qh + 4 * FT_HALF;
    __half* Vl = Qh + 5 * FT_HALF;
    __half* Ph = Qh + 6 * FT_HALF;
    float* Ss = (float*)(sm + F_SS);
    float* Os = (float*)(sm + F_OS);
    float* mrow = (float*)(sm + F_MR);
    float* lrow = mrow + 64;

    const uint32_t sb = smem_u32(sm);
    const int tid = threadIdx.x;
    const int wid = tid >> 5;
    const int wm = wid & 3;
    const int wn = wid >> 2;
    const int b = blockIdx.y >> 4;
    const int h = blockIdx.y & 15;
    const int q0 = blockIdx.x * 64;
    const int r4 = tid >> 2, ln = tid & 3;   // softmax row / quad lane

    // Q tile load (pre-scaled at gemm1): 1024 cp16 chunks
#pragma unroll
    for (int i = 0; i < 4; i++) {
        int idx = tid + i * 256;
        int arr = idx >> 9, e = idx & 511;
        int r = e >> 3, f = e & 7;
        const __half* src = (arr ? g_qkvl : g_qkvh)
            + (size_t)(b * NN + q0 + r) * 3072 + h * DD + f * 8;
        cp16(sb + (uint32_t)arr * 9216 + (uint32_t)(r * FQP + f * 8) * 2, src);
    }
    CP_COMMIT();
    for (int i = tid; i < 64 * FSP; i += 256) Os[i] = 0.0f;
    if (tid < 64) { mrow[tid] = -INFINITY; lrow[tid] = 0.0f; }
    CP_WAIT0();
    __syncthreads();

    for (int kt = 0; kt < 32; kt++) {
        // K/V tiles (hi+lo): 2048 cp16 chunks
#pragma unroll
        for (int i = 0; i < 8; i++) {
            int idx = tid + i * 256;
            int arr = idx >> 9;           // 0:Kh 1:Kl 2:Vh 3:Vl
            int e = idx & 511;
            int r = e >> 3, f = e & 7;
            const __half* srcb = ((arr & 1) ? g_qkvl : g_qkvh)
                + 1024 + (arr >> 1) * 1024;
            const __half* src = srcb
                + (size_t)(b * NN + kt * 64 + r) * 3072 + h * DD + f * 8;
            cp16(sb + 18432 + (uint32_t)arr * 9216 + (uint32_t)(r * FQP + f * 8) * 2, src);
        }
        CP_COMMIT();
        CP_WAIT0();
        __syncthreads();

        // ---- S = Q K^T (3-term) ----
        {
            HC c[2];
            wmma::fill_fragment(c[0], 0.0f);
            wmma::fill_fragment(c[1], 0.0f);
#pragma unroll
            for (int s = 0; s < 4; s++) {
                HA qh_, ql_;
                wmma::load_matrix_sync(qh_, Qh + wm * 16 * FQP + s * 16, FQP);
                wmma::load_matrix_sync(ql_, Ql + wm * 16 * FQP + s * 16, FQP);
#pragma unroll
                for (int j = 0; j < 2; j++) {
                    HBc kh_, kl_;
                    wmma::load_matrix_sync(kh_, Kh + (wn * 32 + j * 16) * FQP + s * 16, FQP);
                    wmma::load_matrix_sync(kl_, Kl + (wn * 32 + j * 16) * FQP + s * 16, FQP);
                    wmma::mma_sync(c[j], qh_, kh_, c[j]);
                    wmma::mma_sync(c[j], qh_, kl_, c[j]);
                    wmma::mma_sync(c[j], ql_, kh_, c[j]);
                }
            }
#pragma unroll
            for (int j = 0; j < 2; j++)
                wmma::store_matrix_sync(Ss + wm * 16 * FSP + wn * 32 + j * 16,
                                        c[j], FSP, wmma::mem_row_major);
        }
        __syncthreads();

        // ---- fused: online softmax + O rescale + P fp16 convert (row-local) ----
        {
            float* sp = Ss + r4 * FSP + ln * 16;
            float4 s0 = *(float4*)(sp + 0),  s1 = *(float4*)(sp + 4);
            float4 s2 = *(float4*)(sp + 8),  s3 = *(float4*)(sp + 12);
            float mo = mrow[r4];
            float mx = fmaxf(fmaxf(fmaxf(s0.x, s0.y), fmaxf(s0.z, s0.w)),
                             fmaxf(fmaxf(s1.x, s1.y), fmaxf(s1.z, s1.w)));
            mx = fmaxf(mx, fmaxf(fmaxf(fmaxf(s2.x, s2.y), fmaxf(s2.z, s2.w)),
                                 fmaxf(fmaxf(s3.x, s3.y), fmaxf(s3.z, s3.w))));
            mx = fmaxf(mx, __shfl_xor_sync(0xffffffffu, mx, 1));
            mx = fmaxf(mx, __shfl_xor_sync(0xffffffffu, mx, 2));
            float mn = fmaxf(mo, mx);
            float sum = 0.0f;
            s0.x = __expf(s0.x - mn); sum += s0.x; s0.y = __expf(s0.y - mn); sum += s0.y;
            s0.z = __expf(s0.z - mn); sum += s0.z; s0.w = __expf(s0.w - mn); sum += s0.w;
            s1.x = __expf(s1.x - mn); sum += s1.x; s1.y = __expf(s1.y - mn); sum += s1.y;
            s1.z = __expf(s1.z - mn); sum += s1.z; s1.w = __expf(s1.w - mn); sum += s1.w;
            s2.x = __expf(s2.x - mn); sum += s2.x; s2.y = __expf(s2.y - mn); sum += s2.y;
            s2.z = __expf(s2.z - mn); sum += s2.z; s2.w = __expf(s2.w - mn); sum += s2.w;
            s3.x = __expf(s3.x - mn); sum += s3.x; s3.y = __expf(s3.y - mn); sum += s3.y;
            s3.z = __expf(s3.z - mn); sum += s3.z; s3.w = __expf(s3.w - mn); sum += s3.w;
            sum += __shfl_xor_sync(0xffffffffu, sum, 1);
            sum += __shfl_xor_sync(0xffffffffu, sum, 2);
            float alpha = __expf(mo - mn);
            if (ln == 0) {
                lrow[r4] = lrow[r4] * alpha + sum;
                mrow[r4] = mn;
            }
            // P -> fp16
            __half2* pp = (__half2*)(Ph + r4 * FQP + ln * 16);
            pp[0] = __halves2half2(__float2half_rn(s0.x), __float2half_rn(s0.y));
            pp[1] = __halves2half2(__float2half_rn(s0.z), __float2half_rn(s0.w));
            pp[2] = __halves2half2(__float2half_rn(s1.x), __float2half_rn(s1.y));
            pp[3] = __halves2half2(__float2half_rn(s1.z), __float2half_rn(s1.w));
            pp[4] = __halves2half2(__float2half_rn(s2.x), __float2half_rn(s2.y));
            pp[5] = __halves2half2(__float2half_rn(s2.z), __float2half_rn(s2.w));
            pp[6] = __halves2half2(__float2half_rn(s3.x), __float2half_rn(s3.y));
            pp[7] = __halves2half2(__float2half_rn(s3.z), __float2half_rn(s3.w));
            // O *= alpha
            float* op = Os + r4 * FSP + ln * 16;
#pragma unroll
            for (int f = 0; f < 4; f++) {
                float4 v = *(float4*)(op + f * 4);
                v.x *= alpha; v.y *= alpha; v.z *= alpha; v.w *= alpha;
                *(float4*)(op + f * 4) = v;
            }
        }
        __syncthreads();

        // ---- O += P V (2-term: Ph*Vh + Ph*Vl) ----
        {
            HC c[2];
#pragma unroll
            for (int j = 0; j < 2; j++)
                wmma::load_matrix_sync(c[j], Os + wm * 16 * FSP + wn * 32 + j * 16,
                                       FSP, wmma::mem_row_major);
#pragma unroll
            for (int s = 0; s < 4; s++) {
                HA p_;
                wmma::load_matrix_sync(p_, Ph + wm * 16 * FQP + s * 16, FQP);
#pragma unroll
                for (int j = 0; j < 2; j++) {
                    HBr vh_, vl_;
                    wmma::load_matrix_sync(vh_, Vh + (s * 16) * FQP + wn * 32 + j * 16, FQP);
                    wmma::load_matrix_sync(vl_, Vl + (s * 16) * FQP + wn * 32 + j * 16, FQP);
                    wmma::mma_sync(c[j], p_, vh_, c[j]);
                    wmma::mma_sync(c[j], p_, vl_, c[j]);
                }
            }
#pragma unroll
            for (int j = 0; j < 2; j++)
                wmma::store_matrix_sync(Os + wm * 16 * FSP + wn * 32 + j * 16,
                                        c[j], FSP, wmma::mem_row_major);
        }
        __syncthreads();
    }

    // Epilogue: normalize, split to fp16 hi/lo for gemm2
    {
        float inv = 1.0f / lrow[r4];
        float* op = Os + r4 * FSP + ln * 16;
        size_t go = (size_t)(b * NN + q0 + r4) * INNER + h * DD + ln * 16;
        __half2* dh = (__half2*)(g_ath + go);
        __half2* dl = (__half2*)(g_atl + go);
#pragma unroll
        for (int f = 0; f < 8; f++) {
            float a = op[f * 2] * inv, c = op[f * 2 + 1] * inv;
            __half ha, la, hc, lc;
            split1(a, ha, la); split1(c, hc, lc);
            dh[f] = __halves2half2(ha, hc);
            dl[f] = __halves2half2(la, lc);
        }
    }
}

// ---------------------------------------------------------------------------
extern "C" void kernel_launch(void* const* d_in, const int* in_sizes, int n_in,
                              void* d_out, int out_size)
{
    const float* x      = (const float*)d_in[0];
    const float* w_qkv  = (const float*)d_in[1];
    const float* w_proj = (const float*)d_in[2];
    const float* b_proj = (const float*)d_in[3];
    float* out = (float*)d_out;

    void *xh, *xl, *wqh, *wql, *wph, *wpl, *qh, *ql, *ath, *atl;
    cudaGetSymbolAddress(&xh, g_xh);   cudaGetSymbolAddress(&xl, g_xl);
    cudaGetSymbolAddress(&wqh, g_wqh); cudaGetSymbolAddress(&wql, g_wql);
    cudaGetSymbolAddress(&wph, g_wph); cudaGetSymbolAddress(&wpl, g_wpl);
    cudaGetSymbolAddress(&qh, g_qkvh); cudaGetSymbolAddress(&ql, g_qkvl);
    cudaGetSymbolAddress(&ath, g_ath); cudaGetSymbolAddress(&atl, g_atl);

    cudaFuncSetAttribute(gemm_h, cudaFuncAttributeMaxDynamicSharedMemorySize, G_SMEM);
    cudaFuncSetAttribute(flash_h, cudaFuncAttributeMaxDynamicSharedMemorySize, F_SMEM);

    // Split inputs into fp16 hi/lo
    splitk<<<4096, 256>>>(x, (__half*)xh, (__half*)xl, 1048576);
    splitk<<<3072, 256>>>(w_qkv, (__half*)wqh, (__half*)wql, 786432);
    splitk<<<1024, 256>>>(w_proj, (__half*)wph, (__half*)wpl, 262144);

    // 1) qkv = x @ w_qkv -> g_qkvh/l (q cols pre-scaled)
    gemm_h<<<dim3(24, 32), 256, G_SMEM>>>(
        (const __half*)xh, (const __half*)xl, (const __half*)wqh, (const __half*)wql,
        nullptr, nullptr, (__half*)qh, (__half*)ql, 4096, 3072, 1024, 0);
    // 2) flash attention -> g_ath/l
    flash_h<<<dim3(32, 32), 256, F_SMEM>>>();
    // 3) out = attn @ w_proj + b_proj (fp32)
    gemm_h<<<dim3(8, 32), 256, G_SMEM>>>(
        (const __half*)ath, (const __half*)atl, (const __half*)wph, (const __half*)wpl,
        out, b_proj, nullptr, nullptr, 4096, 1024, 1024, 1);
}

// round 5
// speedup vs baseline: 4.3176x; 1.4480x over previous
#include <cuda_runtime.h>
#include <cuda_fp16.h>
#include <mma.h>
#include <cstdint>
#include <math.h>

using namespace nvcuda;

#define BB 2
#define NN 2048
#define CC 1024
#define HH 16
#define DD 64
#define INNER 1024
#define QK_SCALE 0.125f

// fp16 hi/lo split scratch
__device__ __half g_xh[4194304],  g_xl[4194304];
__device__ __half g_wqh[3145728], g_wql[3145728];
__device__ __half g_wph[1048576], g_wpl[1048576];
__device__ __half g_qkvh[12582912], g_qkvl[12582912];
__device__ __half g_ath[4194304], g_atl[4194304];

// ---------------------------------------------------------------------------
__device__ __forceinline__ uint32_t smem_u32(const void* p) {
    uint32_t a;
    asm("{ .reg .u64 t; cvta.to.shared.u64 t, %1; cvt.u32.u64 %0, t; }"
        : "=r"(a) : "l"(p));
    return a;
}
__device__ __forceinline__ void cp16(uint32_t dst, const void* src) {
    asm volatile("cp.async.cg.shared.global [%0], [%1], 16;"
                 :: "r"(dst), "l"(src));
}
#define CP_COMMIT() asm volatile("cp.async.commit_group;" ::: "memory")
#define CP_WAIT1()  asm volatile("cp.async.wait_group 1;" ::: "memory")
#define CP_WAIT0()  asm volatile("cp.async.wait_group 0;" ::: "memory")

#define LDSM_X4(r0,r1,r2,r3,addr) \
    asm volatile("ldmatrix.sync.aligned.m8n8.x4.shared.b16 {%0,%1,%2,%3}, [%4];" \
        : "=r"(r0),"=r"(r1),"=r"(r2),"=r"(r3) : "r"(addr))
#define LDSM_X2(r0,r1,addr) \
    asm volatile("ldmatrix.sync.aligned.m8n8.x2.shared.b16 {%0,%1}, [%2];" \
        : "=r"(r0),"=r"(r1) : "r"(addr))
#define LDSM_X2T(r0,r1,addr) \
    asm volatile("ldmatrix.sync.aligned.m8n8.x2.trans.shared.b16 {%0,%1}, [%2];" \
        : "=r"(r0),"=r"(r1) : "r"(addr))
#define MMA16816(c,a,b0,b1) \
    asm volatile("mma.sync.aligned.m16n8k16.row.col.f32.f16.f16.f32 " \
        "{%0,%1,%2,%3},{%4,%5,%6,%7},{%8,%9},{%0,%1,%2,%3};" \
        : "+f"((c)[0]),"+f"((c)[1]),"+f"((c)[2]),"+f"((c)[3]) \
        : "r"((a)[0]),"r"((a)[1]),"r"((a)[2]),"r"((a)[3]),"r"(b0),"r"(b1))

__device__ __forceinline__ uint32_t pk2(float lo, float hi) {
    uint32_t u;
    asm("cvt.rn.f16x2.f32 %0, %1, %2;" : "=r"(u) : "f"(hi), "f"(lo));
    return u;
}
__device__ __forceinline__ void split1(float v, __half& h, __half& l) {
    h = __float2half_rn(v);
    l = __float2half_rn(v - __half2float(h));
}

typedef wmma::fragment<wmma::matrix_a, 16, 16, 16, __half, wmma::row_major> HA;
typedef wmma::fragment<wmma::matrix_b, 16, 16, 16, __half, wmma::row_major> HBr;
typedef wmma::fragment<wmma::accumulator, 16, 16, 16, float> HC;

// ---------------------------------------------------------------------------
// Pre-split kernel: fp32 -> (hi, lo) fp16
// ---------------------------------------------------------------------------
__global__ __launch_bounds__(256) void splitk(
    const float* __restrict__ s, __half* __restrict__ hi,
    __half* __restrict__ lo, int n4)
{
    int i = blockIdx.x * 256 + threadIdx.x;
    if (i >= n4) return;
    float4 v = ((const float4*)s)[i];
    __half h0, h1, h2, h3, l0, l1, l2, l3;
    split1(v.x, h0, l0); split1(v.y, h1, l1);
    split1(v.z, h2, l2); split1(v.w, h3, l3);
    ((__half2*)hi)[2 * i]     = __halves2half2(h0, h1);
    ((__half2*)hi)[2 * i + 1] = __halves2half2(h2, h3);
    ((__half2*)lo)[2 * i]     = __halves2half2(l0, l1);
    ((__half2*)lo)[2 * i + 1] = __halves2half2(l2, l3);
}

// ---------------------------------------------------------------------------
// fp16 split GEMM (wmma): 128x128 tile, 256 thr, K-step 32, 2-stage cp.async.
// ---------------------------------------------------------------------------
#define GP_A 40
#define GP_B 136
#define A_HALF (128 * GP_A)
#define B_HALF (32 * GP_B)
#define G_ABYTES (A_HALF * 2)
#define G_BBYTES (B_HALF * 2)
#define G_STAGE (2 * G_ABYTES + 2 * G_BBYTES)
#define G_SMEM (2 * G_STAGE)

__device__ __forceinline__ void g_issue(
    uint32_t sb, const __half* Ah, const __half* Al,
    const __half* Bh, const __half* Bl,
    int m0, int n0, int K, int N, int kt, int tid)
{
    uint32_t st = sb + (uint32_t)(kt & 1) * G_STAGE;
#pragma unroll
    for (int i = 0; i < 4; i++) {
        int idx = tid + i * 256;
        int arr = idx >> 9, e = idx & 511;
        int r = e >> 2, f = e & 3;
        const __half* src = (arr ? Al : Ah) + (size_t)(m0 + r) * K + kt * 32 + f * 8;
        cp16(st + (uint32_t)arr * G_ABYTES + (uint32_t)(r * GP_A + f * 8) * 2, src);
    }
#pragma unroll
    for (int i = 0; i < 4; i++) {
        int idx = tid + i * 256;
        int arr = idx >> 9, e = idx & 511;
        int r = e >> 4, f = e & 15;
        const __half* src = (arr ? Bl : Bh) + (size_t)(kt * 32 + r) * N + n0 + f * 8;
        cp16(st + 2 * G_ABYTES + (uint32_t)arr * G_BBYTES
                + (uint32_t)(r * GP_B + f * 8) * 2, src);
    }
}

__global__ __launch_bounds__(256, 2) void gemm_h(
    const __half* __restrict__ Ah, const __half* __restrict__ Al,
    const __half* __restrict__ Bh, const __half* __restrict__ Bl,
    float* __restrict__ Cout, const float* __restrict__ bias,
    __half* __restrict__ Ch, __half* __restrict__ Cl,
    int M, int N, int K, int mode)
{
    extern __shared__ char sm[];
    const uint32_t sb = smem_u32(sm);
    const int tid = threadIdx.x;
    const int wid = tid >> 5;
    const int wm = wid & 3;
    const int wn = wid >> 2;
    const int m0 = blockIdx.y * 128;
    const int n0 = blockIdx.x * 128;

    HC acc[2][4];
#pragma unroll
    for (int i = 0; i < 2; i++)
#pragma unroll
        for (int j = 0; j < 4; j++) wmma::fill_fragment(acc[i][j], 0.0f);

    const int nkt = K / 32;
    g_issue(sb, Ah, Al, Bh, Bl, m0, n0, K, N, 0, tid); CP_COMMIT();
    g_issue(sb, Ah, Al, Bh, Bl, m0, n0, K, N, 1, tid); CP_COMMIT();

    for (int kt = 0; kt < nkt; kt++) {
        CP_WAIT1();
        __syncthreads();
        const __half* st  = (const __half*)(sm + (size_t)(kt & 1) * G_STAGE);
        const __half* Ash = st;
        const __half* Asl = st + A_HALF;
        const __half* Bsh = st + 2 * A_HALF;
        const __half* Bsl = st + 2 * A_HALF + B_HALF;

#pragma unroll
        for (int s = 0; s < 2; s++) {
            HA ah[2], al[2];
#pragma unroll
            for (int i = 0; i < 2; i++) {
                wmma::load_matrix_sync(ah[i], Ash + (wm * 32 + i * 16) * GP_A + s * 16, GP_A);
                wmma::load_matrix_sync(al[i], Asl + (wm * 32 + i * 16) * GP_A + s * 16, GP_A);
            }
#pragma unroll
            for (int j = 0; j < 4; j++) {
                HBr bh, bl;
                wmma::load_matrix_sync(bh, Bsh + (s * 16) * GP_B + wn * 64 + j * 16, GP_B);
                wmma::load_matrix_sync(bl, Bsl + (s * 16) * GP_B + wn * 64 + j * 16, GP_B);
#pragma unroll
                for (int i = 0; i < 2; i++) {
                    wmma::mma_sync(acc[i][j], ah[i], bh, acc[i][j]);
                    wmma::mma_sync(acc[i][j], ah[i], bl, acc[i][j]);
                    wmma::mma_sync(acc[i][j], al[i], bh, acc[i][j]);
                }
            }
        }
        __syncthreads();
        if (kt + 2 < nkt)
            g_issue(sb, Ah, Al, Bh, Bl, m0, n0, K, N, kt + 2, tid);
        CP_COMMIT();
    }
    CP_WAIT0();
    __syncthreads();

    float* Cs = (float*)sm;
#pragma unroll
    for (int i = 0; i < 2; i++)
#pragma unroll
        for (int j = 0; j < 4; j++)
            wmma::store_matrix_sync(Cs + (wm * 32 + i * 16) * 128 + wn * 64 + j * 16,
                                    acc[i][j], 128, wmma::mem_row_major);
    __syncthreads();
#pragma unroll
    for (int i = 0; i < 16; i++) {
        int idx = tid + i * 256;
        int r = idx >> 5, f = idx & 31;
        float4 v = *(float4*)(Cs + r * 128 + f * 4);
        int gc = n0 + f * 4;
        if (mode == 1) {
            const float* bp = bias + gc;
            v.x += bp[0]; v.y += bp[1]; v.z += bp[2]; v.w += bp[3];
            *(float4*)(Cout + (size_t)(m0 + r) * N + gc) = v;
        } else {
            float sc = (gc < 1024) ? QK_SCALE : 1.0f;
            v.x *= sc; v.y *= sc; v.z *= sc; v.w *= sc;
            __half h0, h1, h2, h3, l0, l1, l2, l3;
            split1(v.x, h0, l0); split1(v.y, h1, l1);
            split1(v.z, h2, l2); split1(v.w, h3, l3);
            __half2* ph = (__half2*)(Ch + (size_t)(m0 + r) * N + gc);
            __half2* pl = (__half2*)(Cl + (size_t)(m0 + r) * N + gc);
            ph[0] = __halves2half2(h0, h1); ph[1] = __halves2half2(h2, h3);
            pl[0] = __halves2half2(l0, l1); pl[1] = __halves2half2(l2, l3);
        }
    }
}

// ---------------------------------------------------------------------------
// Flash attention, register-resident mma.sync.m16n8k16 (FA2 style).
// Block = (b, h, 128-q-rows); 8 warps x 16 rows. Bc = 64. QK 3-term, PV 2-term.
// smem: double-buffered K/V (hi/lo) tiles; Q staged once then lives in regs.
// ---------------------------------------------------------------------------
#define FPK 72                     // smem pitch in halves (144 B)
#define KV_TILE 4608               // 64*72 halves per tile
#define KV_BUF 18432               // 4 tiles (Kh,Kl,Vh,Vl) in halves
#define F_SMEM (2 * KV_BUF * 2)    // 73728 bytes

__device__ __forceinline__ void kv_issue(uint32_t sb, int b, int h, int kt,
                                         int buf, int tid)
{
    size_t rowbase = (size_t)(b * NN + kt * 64) * 3072 + 1024 + h * 64;
#pragma unroll
    for (int i = 0; i < 8; i++) {
        int idx = tid + i * 256;
        int arr = idx >> 9;           // 0:Kh 1:Kl 2:Vh 3:Vl
        int e = idx & 511;
        int r = e >> 3, f = e & 7;
        const __half* src = ((arr & 1) ? g_qkvl : g_qkvh)
            + rowbase + (size_t)(arr >> 1) * 1024 + (size_t)r * 3072 + f * 8;
        uint32_t dst = sb + (uint32_t)(buf * KV_BUF + arr * KV_TILE + r * FPK + f * 8) * 2;
        cp16(dst, src);
    }
}

__global__ __launch_bounds__(256, 2) void flash_r()
{
    extern __shared__ char sm[];
    const uint32_t sb = smem_u32(sm);
    const int tid = threadIdx.x;
    const int w = tid >> 5;
    const int lane = tid & 31;
    const int l15 = lane & 15;
    const int g = lane >> 2;          // groupID (row within 8)
    const int tg = lane & 3;          // thread-in-group
    const int b = blockIdx.y >> 4;
    const int h = blockIdx.y & 15;
    const int q0 = blockIdx.x * 128;

    // ---- stage Q into buf1 region, extract to registers ----
    {
        size_t qrowbase = (size_t)(b * NN + q0) * 3072 + h * 64;
#pragma unroll
        for (int i = 0; i < 8; i++) {
            int idx = tid + i * 256;
            int arr = idx >> 10;          // 0: Qh, 1: Ql
            int e = idx & 1023;
            int r = e >> 3, f = e & 7;
            const __half* src = (arr ? g_qkvl : g_qkvh)
                + qrowbase + (size_t)r * 3072 + f * 8;
            uint32_t dst = sb + (uint32_t)(KV_BUF + arr * 9216 + r * FPK + f * 8) * 2;
            cp16(dst, src);
        }
    }
    kv_issue(sb, b, h, 0, 0, tid);
    CP_COMMIT();
    CP_WAIT0();
    __syncthreads();

    uint32_t qh[4][4], ql[4][4];
    {
        uint32_t qrow = (uint32_t)(w * 16 + l15);
#pragma unroll
        for (int t = 0; t < 4; t++) {
            uint32_t a = sb + (uint32_t)(KV_BUF + qrow * FPK + t * 16 + (lane >> 4) * 8) * 2;
            LDSM_X4(qh[t][0], qh[t][1], qh[t][2], qh[t][3], a);
            LDSM_X4(ql[t][0], ql[t][1], ql[t][2], ql[t][3], a + 9216 * 2);
        }
    }
    __syncthreads();   // Q region (buf1) safe to overwrite after this

    float o[8][4];
#pragma unroll
    for (int j = 0; j < 8; j++)
#pragma unroll
        for (int e = 0; e < 4; e++) o[j][e] = 0.0f;
    float m0 = -INFINITY, m1 = -INFINITY, ls0 = 0.0f, ls1 = 0.0f;

    for (int kt = 0; kt < 32; kt++) {
        CP_WAIT0();          // KV(kt) landed (self)
        __syncthreads();     // visible to all; previous compute done
        if (kt < 31) {
            kv_issue(sb, b, h, kt + 1, (kt + 1) & 1, tid);
            CP_COMMIT();
        }
        const uint32_t bufb = sb + (uint32_t)((kt & 1) * KV_BUF) * 2;

        // ---- S = Q K^T (3-term) ----
        float s[8][4];
#pragma unroll
        for (int j = 0; j < 8; j++)
#pragma unroll
            for (int e = 0; e < 4; e++) s[j][e] = 0.0f;
#pragma unroll
        for (int t = 0; t < 4; t++) {
#pragma unroll
            for (int j = 0; j < 8; j++) {
                uint32_t ka = bufb + (uint32_t)((8 * j + (l15 & 7)) * FPK
                                + t * 16 + (l15 >> 3) * 8) * 2;
                uint32_t bh0, bh1, bl0, bl1;
                LDSM_X2(bh0, bh1, ka);
                LDSM_X2(bl0, bl1, ka + KV_TILE * 2);
                MMA16816(s[j], qh[t], bh0, bh1);
                MMA16816(s[j], qh[t], bl0, bl1);
                MMA16816(s[j], ql[t], bh0, bh1);
            }
        }

        // ---- online softmax in registers (rows g and g+8) ----
        float mx0 = s[0][0], mx1 = s[0][2];
#pragma unroll
        for (int j = 0; j < 8; j++) {
            mx0 = fmaxf(mx0, fmaxf(s[j][0], s[j][1]));
            mx1 = fmaxf(mx1, fmaxf(s[j][2], s[j][3]));
        }
        mx0 = fmaxf(mx0, __shfl_xor_sync(0xffffffffu, mx0, 1));
        mx0 = fmaxf(mx0, __shfl_xor_sync(0xffffffffu, mx0, 2));
        mx1 = fmaxf(mx1, __shfl_xor_sync(0xffffffffu, mx1, 1));
        mx1 = fmaxf(mx1, __shfl_xor_sync(0xffffffffu, mx1, 2));
        float m0n = fmaxf(m0, mx0), m1n = fmaxf(m1, mx1);
        float a0 = __expf(m0 - m0n), a1 = __expf(m1 - m1n);
        float sum0 = 0.0f, sum1 = 0.0f;
#pragma unroll
        for (int j = 0; j < 8; j++) {
            s[j][0] = __expf(s[j][0] - m0n); sum0 += s[j][0];
            s[j][1] = __expf(s[j][1] - m0n); sum0 += s[j][1];
            s[j][2] = __expf(s[j][2] - m1n); sum1 += s[j][2];
            s[j][3] = __expf(s[j][3] - m1n); sum1 += s[j][3];
        }
        sum0 += __shfl_xor_sync(0xffffffffu, sum0, 1);
        sum0 += __shfl_xor_sync(0xffffffffu, sum0, 2);
        sum1 += __shfl_xor_sync(0xffffffffu, sum1, 1);
        sum1 += __shfl_xor_sync(0xffffffffu, sum1, 2);
        ls0 = ls0 * a0 + sum0; ls1 = ls1 * a1 + sum1;
        m0 = m0n; m1 = m1n;

        // P -> fp16 A-fragments; rescale O
        uint32_t pa[4][4];
#pragma unroll
        for (int t = 0; t < 4; t++) {
            pa[t][0] = pk2(s[2 * t][0],     s[2 * t][1]);
            pa[t][1] = pk2(s[2 * t][2],     s[2 * t][3]);
            pa[t][2] = pk2(s[2 * t + 1][0], s[2 * t + 1][1]);
            pa[t][3] = pk2(s[2 * t + 1][2], s[2 * t + 1][3]);
        }
#pragma unroll
        for (int j = 0; j < 8; j++) {
            o[j][0] *= a0; o[j][1] *= a0;
            o[j][2] *= a1; o[j][3] *= a1;
        }

        // ---- O += P V (2-term) ----
#pragma unroll
        for (int t = 0; t < 4; t++) {
#pragma unroll
            for (int j = 0; j < 8; j++) {
                uint32_t va = bufb + (uint32_t)(2 * KV_TILE
                                + (16 * t + l15) * FPK + 8 * j) * 2;
                uint32_t v0, v1, u0, u1;
                LDSM_X2T(v0, v1, va);
                LDSM_X2T(u0, u1, va + KV_TILE * 2);
                MMA16816(o[j], pa[t], v0, v1);
                MMA16816(o[j], pa[t], u0, u1);
            }
        }
    }

    // ---- epilogue: normalize, split hi/lo, write g_ath/g_atl ----
    {
        float inv0 = 1.0f / ls0, inv1 = 1.0f / ls1;
        size_t row0 = (size_t)(b * NN + q0 + w * 16 + g);
        size_t row1 = row0 + 8;
        int col = h * 64 + 2 * tg;
#pragma unroll
        for (int j = 0; j < 8; j++) {
            size_t i0 = row0 * 1024 + col + 8 * j;
            size_t i1 = row1 * 1024 + col + 8 * j;
            float v00 = o[j][0] * inv0, v01 = o[j][1] * inv0;
            float v10 = o[j][2] * inv1, v11 = o[j][3] * inv1;
            __half h0, l0, h1, l1;
            split1(v00, h0, l0); split1(v01, h1, l1);
            *(__half2*)(g_ath + i0) = __halves2half2(h0, h1);
            *(__half2*)(g_atl + i0) = __halves2half2(l0, l1);
            split1(v10, h0, l0); split1(v11, h1, l1);
            *(__half2*)(g_ath + i1) = __halves2half2(h0, h1);
            *(__half2*)(g_atl + i1) = __halves2half2(l0, l1);
        }
    }
}

// ---------------------------------------------------------------------------
extern "C" void kernel_launch(void* const* d_in, const int* in_sizes, int n_in,
                              void* d_out, int out_size)
{
    const float* x      = (const float*)d_in[0];
    const float* w_qkv  = (const float*)d_in[1];
    const float* w_proj = (const float*)d_in[2];
    const float* b_proj = (const float*)d_in[3];
    float* out = (float*)d_out;

    void *xh, *xl, *wqh, *wql, *wph, *wpl, *qh, *ql, *ath, *atl;
    cudaGetSymbolAddress(&xh, g_xh);   cudaGetSymbolAddress(&xl, g_xl);
    cudaGetSymbolAddress(&wqh, g_wqh); cudaGetSymbolAddress(&wql, g_wql);
    cudaGetSymbolAddress(&wph, g_wph); cudaGetSymbolAddress(&wpl, g_wpl);
    cudaGetSymbolAddress(&qh, g_qkvh); cudaGetSymbolAddress(&ql, g_qkvl);
    cudaGetSymbolAddress(&ath, g_ath); cudaGetSymbolAddress(&atl, g_atl);

    cudaFuncSetAttribute(gemm_h, cudaFuncAttributeMaxDynamicSharedMemorySize, G_SMEM);
    cudaFuncSetAttribute(flash_r, cudaFuncAttributeMaxDynamicSharedMemorySize, F_SMEM);

    splitk<<<4096, 256>>>(x, (__half*)xh, (__half*)xl, 1048576);
    splitk<<<3072, 256>>>(w_qkv, (__half*)wqh, (__half*)wql, 786432);
    splitk<<<1024, 256>>>(w_proj, (__half*)wph, (__half*)wpl, 262144);

    // 1) qkv = x @ w_qkv -> g_qkvh/l (q columns pre-scaled by 1/8)
    gemm_h<<<dim3(24, 32), 256, G_SMEM>>>(
        (const __half*)xh, (const __half*)xl, (const __half*)wqh, (const __half*)wql,
        nullptr, nullptr, (__half*)qh, (__half*)ql, 4096, 3072, 1024, 0);
    // 2) flash attention -> g_ath/l
    flash_r<<<dim3(16, 32), 256, F_SMEM>>>();
    // 3) out = attn @ w_proj + b_proj
    gemm_h<<<dim3(8, 32), 256, G_SMEM>>>(
        (const __half*)ath, (const __half*)atl, (const __half*)wph, (const __half*)wpl,
        out, b_proj, nullptr, nullptr, 4096, 1024, 1024, 1);
}